// round 7
// baseline (speedup 1.0000x reference)
#include <cuda_runtime.h>
#include <math.h>

#define TT 4096
#define EE 768
#define HH 12
#define DD 64
#define WIN 512
#define OUT_ELEMS (TT*EE)                 // 3145728
#define ATTN_ELEMS ((size_t)HH*TT*TT)     // 201326592

typedef unsigned long long ull;

// f32x2 packed-FMA helpers (sm_100+ PTX; ptxas never auto-fuses these)
#define PACK2(d, x)  asm("mov.b64 %0, {%1, %2};" : "=l"(d) : "f"(x), "f"(x))
#define FMA2(d, a, b) asm("fma.rn.f32x2 %0, %1, %2, %0;" : "+l"(d) : "l"(a), "l"(b))
#define UNPACK2(lo, hi, v) asm("mov.b64 {%0, %1}, %2;" : "=f"(lo), "=f"(hi) : "l"(v))

// ---------------- scratch (device globals: allocation-free) ----------------
__device__ __align__(16) float g_Q[TT*EE];
__device__ __align__(16) float g_K[TT*EE];
__device__ __align__(16) float g_V[TT*EE];
__device__ __align__(16) float g_ctx[TT*EE];
__device__ __align__(16) float g_d[HH*TT];

// ---------------- fp32 GEMM with f32x2: C[4096,768] = A[4096,768] @ W[768,768]
// BM=128, BN=64, BK=16, 256 threads, 8x4 micro-tile (4 cols = 2 f32x2 pairs).
__global__ __launch_bounds__(256) void sgemm_kernel(
    const float* __restrict__ A,
    const float* __restrict__ W0, const float* __restrict__ W1, const float* __restrict__ W2,
    float* __restrict__ Cout, int mode)
{
    const float* W;
    float* C;
    const float* Ain;
    if (mode == 0) {
        int z = blockIdx.z;
        W = (z == 0) ? W0 : (z == 1) ? W1 : W2;
        C = (z == 0) ? g_Q : (z == 1) ? g_K : g_V;
        Ain = A;
    } else {
        W = W0; C = Cout; Ain = g_ctx;
    }

    __shared__ float As[16][128];
    __shared__ float Ws[16][64];

    int tid = threadIdx.x;
    int tx = tid & 15, ty = tid >> 4;
    int n0 = blockIdx.x * 64;
    int m0 = blockIdx.y * 128;

    ull acc[8][2];
    #pragma unroll
    for (int r = 0; r < 8; r++) { acc[r][0] = 0ULL; acc[r][1] = 0ULL; }

    for (int k0 = 0; k0 < 768; k0 += 16) {
        #pragma unroll
        for (int it = 0; it < 2; it++) {
            int idx = tid + it * 256;
            int row = idx >> 2;
            int kq = (idx & 3) * 4;
            float4 v = *(const float4*)(Ain + (size_t)(m0 + row) * 768 + k0 + kq);
            As[kq + 0][row] = v.x;
            As[kq + 1][row] = v.y;
            As[kq + 2][row] = v.z;
            As[kq + 3][row] = v.w;
        }
        {
            int kk = tid >> 4;
            int nq = (tid & 15) * 4;
            *(float4*)&Ws[kk][nq] = *(const float4*)(W + (size_t)(k0 + kk) * 768 + n0 + nq);
        }
        __syncthreads();

        #pragma unroll
        for (int kk = 0; kk < 16; kk++) {
            float4 a0 = *(float4*)&As[kk][ty * 8];
            float4 a1 = *(float4*)&As[kk][ty * 8 + 4];
            ull Ap[8];
            PACK2(Ap[0], a0.x); PACK2(Ap[1], a0.y); PACK2(Ap[2], a0.z); PACK2(Ap[3], a0.w);
            PACK2(Ap[4], a1.x); PACK2(Ap[5], a1.y); PACK2(Ap[6], a1.z); PACK2(Ap[7], a1.w);
            ull b0 = *(const ull*)&Ws[kk][tx * 4];      // 16B-aligned
            ull b1 = *(const ull*)&Ws[kk][tx * 4 + 2];
            #pragma unroll
            for (int r = 0; r < 8; r++) {
                FMA2(acc[r][0], Ap[r], b0);
                FMA2(acc[r][1], Ap[r], b1);
            }
        }
        __syncthreads();
    }

    #pragma unroll
    for (int r = 0; r < 8; r++) {
        float4 v;
        UNPACK2(v.x, v.y, acc[r][0]);
        UNPACK2(v.z, v.w, acc[r][1]);
        *(float4*)(C + (size_t)(m0 + ty * 8 + r) * 768 + n0 + tx * 4) = v;
    }
}

// ---------------- d bias: d[h,t] = K[t]·u[h] - mean_t(K[t]·u[h]) ------------
__global__ __launch_bounds__(1024) void dbias_kernel(const float* __restrict__ u)
{
    int h = blockIdx.x, tid = threadIdx.x;
    __shared__ float su[64];
    __shared__ float red[32];
    if (tid < 64) su[tid] = u[h * 64 + tid];
    __syncthreads();

    float vals[4];
    float lsum = 0.f;
    #pragma unroll
    for (int j = 0; j < 4; j++) {
        int t = j * 1024 + tid;
        const float4* kp = (const float4*)(g_K + (size_t)t * 768 + h * 64);
        float dot = 0.f;
        #pragma unroll
        for (int q = 0; q < 16; q++) {
            float4 kv = kp[q];
            dot += kv.x * su[q * 4] + kv.y * su[q * 4 + 1] + kv.z * su[q * 4 + 2] + kv.w * su[q * 4 + 3];
        }
        vals[j] = dot;
        lsum += dot;
    }
    #pragma unroll
    for (int o = 16; o > 0; o >>= 1) lsum += __shfl_xor_sync(0xffffffffu, lsum, o);
    if ((tid & 31) == 0) red[tid >> 5] = lsum;
    __syncthreads();
    if (tid < 32) {
        float v = red[tid];
        #pragma unroll
        for (int o = 16; o > 0; o >>= 1) v += __shfl_xor_sync(0xffffffffu, v, o);
        if (tid == 0) red[0] = v * (1.0f / 4096.0f);
    }
    __syncthreads();
    float mean = red[0];
    #pragma unroll
    for (int j = 0; j < 4; j++)
        g_d[h * 4096 + j * 1024 + tid] = vals[j] - mean;
}

// ---------------- attention: 64 query rows per block -----------------------
// smem: sQq/sKq [64][65] row-major; sQkT/sKkT [64][66] d-major (transposed,
// even stride for LDS.64); sKkT reused row-major [64][66] as V tile in phase 3.
// sL 64x577, sd 576, rowS 64.
#define LW 577
#define SMEM_FLOATS (2*64*65 + 2*64*66 + 64*LW + 576 + 64)
#define SMEM_BYTES (SMEM_FLOATS * 4)

__global__ __launch_bounds__(256) void attn_kernel(
    const float* __restrict__ gates, float* __restrict__ attn_out)
{
    extern __shared__ float sm[];
    float (*sQq)[65] = (float(*)[65])sm;
    float (*sKq)[65] = sQq + 64;
    float (*sQkT)[66] = (float(*)[66])(sKq + 64);   // [d][col]
    float (*sKkT)[66] = sQkT + 64;                  // [d][col]; also V [row][col]
    float* sL = (float*)(sKkT + 64);      // 64 * 577
    float* sd = sL + 64 * LW;             // 576
    float* rowS = sd + 576;               // 64 (1/rowsum)

    int h = blockIdx.y;
    int t0 = blockIdx.x * 64;
    int tid = threadIdx.x;
    int sb = t0 - 512; if (sb < 0) sb = 0;
    int L = t0 + 64 - sb;                 // multiple of 64, <= 576

    // ---- fused zero-fill of this block's out-of-band attn region ----
    // rows [t0,t0+64) of head h: cols [0,sb) and [t0+64,TT). Fire-and-forget
    // stores; they drain on the idle DRAM path while we do FFMA below.
    {
        const float4 z4 = make_float4(0.f, 0.f, 0.f, 0.f);
        size_t rowbase = (size_t)h * TT * TT + (size_t)t0 * TT;
        int leftq = sb >> 2;                   // sb multiple of 64
        int right0 = t0 + 64;
        int rightq = (TT - right0) >> 2;
        for (int r = 0; r < 64; r++) {
            float4* bp = (float4*)(attn_out + rowbase + (size_t)r * TT);
            for (int c = tid; c < leftq; c += 256) bp[c] = z4;
            float4* rp4 = (float4*)(attn_out + rowbase + (size_t)r * TT + right0);
            for (int c = tid; c < rightq; c += 256) rp4[c] = z4;
        }
    }

    // gate softmax (every thread, cheap + uniform)
    float g0 = gates[h * 3 + 0], g1 = gates[h * 3 + 1], g2 = gates[h * 3 + 2];
    float gm = fmaxf(g0, fmaxf(g1, g2));
    float e0 = __expf(g0 - gm), e1 = __expf(g1 - gm), e2 = __expf(g2 - gm);
    float gi = 1.0f / (e0 + e1 + e2);
    float wstd = e0 * gi, wrec = e1 * gi, wdisc = e2 * gi;

    // load Q, K for query rows (row-major, scalar smem stores) + d band
    for (int i = tid; i < 64 * 16; i += 256) {
        int row = i >> 4;
        int c4 = (i & 15) * 4;
        float4 q = *(const float4*)(g_Q + (size_t)(t0 + row) * 768 + h * 64 + c4);
        float4 k = *(const float4*)(g_K + (size_t)(t0 + row) * 768 + h * 64 + c4);
        sQq[row][c4 + 0] = q.x; sQq[row][c4 + 1] = q.y; sQq[row][c4 + 2] = q.z; sQq[row][c4 + 3] = q.w;
        sKq[row][c4 + 0] = k.x; sKq[row][c4 + 1] = k.y; sKq[row][c4 + 2] = k.z; sKq[row][c4 + 3] = k.w;
    }
    for (int i = tid; i < L; i += 256) sd[i] = g_d[h * 4096 + sb + i];

    int tx = tid & 15, ty = tid >> 4;
    int i0 = ty * 4, j0 = tx * 4;
    int kt_lo = sb >> 6, kt_hi = t0 >> 6;

    // ---- phase 1: banded logits into sL ----
    for (int kt = kt_lo; kt <= kt_hi; kt++) {
        int s0 = kt * 64;
        __syncthreads();
        // load key-block Q,K transposed: sXkT[d][col] = X[s0+col][d]
        for (int i = tid; i < 64 * 16; i += 256) {
            int row = i >> 4;
            int c4 = (i & 15) * 4;
            float4 q = *(const float4*)(g_Q + (size_t)(s0 + row) * 768 + h * 64 + c4);
            float4 k = *(const float4*)(g_K + (size_t)(s0 + row) * 768 + h * 64 + c4);
            sQkT[c4 + 0][row] = q.x; sQkT[c4 + 1][row] = q.y; sQkT[c4 + 2][row] = q.z; sQkT[c4 + 3][row] = q.w;
            sKkT[c4 + 0][row] = k.x; sKkT[c4 + 1][row] = k.y; sKkT[c4 + 2][row] = k.z; sKkT[c4 + 3][row] = k.w;
        }
        __syncthreads();

        ull acc1[4][2], acc2[4][2];
        #pragma unroll
        for (int r = 0; r < 4; r++) {
            acc1[r][0] = 0ULL; acc1[r][1] = 0ULL;
            acc2[r][0] = 0ULL; acc2[r][1] = 0ULL;
        }

        #pragma unroll 8
        for (int d = 0; d < 64; d++) {
            ull Ap[4], KEp[4];
            #pragma unroll
            for (int r = 0; r < 4; r++) {
                PACK2(Ap[r],  sQq[i0 + r][d]);
                PACK2(KEp[r], sKq[i0 + r][d]);
            }
            ull B0  = *(const ull*)&sKkT[d][j0];      // (66*d + j0) even -> 8B aligned
            ull B1  = *(const ull*)&sKkT[d][j0 + 2];
            ull QK0 = *(const ull*)&sQkT[d][j0];
            ull QK1 = *(const ull*)&sQkT[d][j0 + 2];
            #pragma unroll
            for (int r = 0; r < 4; r++) {
                FMA2(acc1[r][0], Ap[r],  B0);
                FMA2(acc1[r][1], Ap[r],  B1);
                FMA2(acc2[r][0], KEp[r], QK0);
                FMA2(acc2[r][1], KEp[r], QK1);
            }
        }

        int soff = s0 - sb;
        #pragma unroll
        for (int r = 0; r < 4; r++) {
            int t = t0 + i0 + r;
            float a1v[4], a2v[4];
            UNPACK2(a1v[0], a1v[1], acc1[r][0]);
            UNPACK2(a1v[2], a1v[3], acc1[r][1]);
            UNPACK2(a2v[0], a2v[1], acc2[r][0]);
            UNPACK2(a2v[2], a2v[3], acc2[r][1]);
            #pragma unroll
            for (int c = 0; c < 4; c++) {
                int s = s0 + j0 + c;
                float v;
                if (s <= t && (t - s) <= 512)
                    v = (wstd * a1v[c] + wrec * a2v[c]) * 0.125f + wdisc * sd[soff + j0 + c];
                else
                    v = -1e30f;
                sL[(i0 + r) * LW + soff + j0 + c] = v;
            }
        }
    }
    __syncthreads();

    // ---- phase 2a: per-row max + exp (in place) + sum; 4 threads per row ----
    {
        int row = tid >> 2, l4 = tid & 3;
        float* rp = sL + row * LW;
        float m = -1e30f;
        for (int c = l4; c < L; c += 4) m = fmaxf(m, rp[c]);
        m = fmaxf(m, __shfl_xor_sync(0xffffffffu, m, 1));
        m = fmaxf(m, __shfl_xor_sync(0xffffffffu, m, 2));
        float s = 0.f;
        for (int c = l4; c < L; c += 4) {
            float ev = __expf(rp[c] - m);
            rp[c] = ev;
            s += ev;
        }
        s += __shfl_xor_sync(0xffffffffu, s, 1);
        s += __shfl_xor_sync(0xffffffffu, s, 2);
        if (l4 == 0) rowS[row] = 1.0f / s;
    }
    __syncthreads();

    // ---- phase 2b: write normalized attn band to gmem ----
    {
        size_t base = (size_t)h * TT * TT + (size_t)t0 * TT + sb;
        for (int i = 0; i < 64; i++) {
            float invs = rowS[i];
            const float* rp = sL + i * LW;
            float* op = attn_out + base + (size_t)i * TT;
            for (int c = tid; c < L; c += 256)
                op[c] = rp[c] * invs;
        }
    }

    // ---- phase 3: ctx = (exp) @ V, scaled by 1/rowsum at the end ----
    ull acc[4][2];
    #pragma unroll
    for (int r = 0; r < 4; r++) { acc[r][0] = 0ULL; acc[r][1] = 0ULL; }

    float (*sV)[66] = sKkT;   // reuse, now row-major [row][col]

    for (int kt = kt_lo; kt <= kt_hi; kt++) {
        int s0 = kt * 64;
        __syncthreads();
        for (int i = tid; i < 64 * 16; i += 256) {
            int row = i >> 4;
            int c4 = (i & 15) * 4;
            float4 v = *(const float4*)(g_V + (size_t)(s0 + row) * 768 + h * 64 + c4);
            sV[row][c4 + 0] = v.x; sV[row][c4 + 1] = v.y; sV[row][c4 + 2] = v.z; sV[row][c4 + 3] = v.w;
        }
        __syncthreads();
        int soff = s0 - sb;
        #pragma unroll 8
        for (int s = 0; s < 64; s++) {
            ull Pp[4];
            #pragma unroll
            for (int r = 0; r < 4; r++) PACK2(Pp[r], sL[(i0 + r) * LW + soff + s]);
            ull V0 = *(const ull*)&sV[s][j0];       // (66*s + j0) even -> aligned
            ull V1 = *(const ull*)&sV[s][j0 + 2];
            #pragma unroll
            for (int r = 0; r < 4; r++) {
                FMA2(acc[r][0], Pp[r], V0);
                FMA2(acc[r][1], Pp[r], V1);
            }
        }
    }

    #pragma unroll
    for (int r = 0; r < 4; r++) {
        float invs = rowS[i0 + r];
        float v0, v1, v2, v3;
        UNPACK2(v0, v1, acc[r][0]);
        UNPACK2(v2, v3, acc[r][1]);
        float* cp = g_ctx + (size_t)(t0 + i0 + r) * 768 + h * 64 + j0;
        cp[0] = v0 * invs; cp[1] = v1 * invs; cp[2] = v2 * invs; cp[3] = v3 * invs;
    }
}

// ---------------- launch ----------------------------------------------------
extern "C" void kernel_launch(void* const* d_in, const int* in_sizes, int n_in,
                              void* d_out, int out_size)
{
    const float* x     = (const float*)d_in[0];
    const float* Wq    = (const float*)d_in[1];
    const float* Wk    = (const float*)d_in[2];
    const float* Wv    = (const float*)d_in[3];
    const float* Wo    = (const float*)d_in[4];
    const float* gates = (const float*)d_in[5];
    const float* u     = (const float*)d_in[6];
    float* out  = (float*)d_out;
    float* attn = out + OUT_ELEMS;

    cudaFuncSetAttribute(attn_kernel, cudaFuncAttributeMaxDynamicSharedMemorySize, SMEM_BYTES);

    // QKV projections
    dim3 gq(12, 32, 3);
    sgemm_kernel<<<gq, 256>>>(x, Wq, Wk, Wv, nullptr, 0);

    // d bias from K
    dbias_kernel<<<12, 1024>>>(u);

    // banded gated attention (writes zeros + attn band + g_ctx; no memset needed)
    dim3 ga(64, 12, 1);
    attn_kernel<<<ga, 256, SMEM_BYTES>>>(gates, attn);

    // output projection
    dim3 go(12, 32, 1);
    sgemm_kernel<<<go, 256>>>(nullptr, Wo, nullptr, nullptr, out, 1);
}

// round 9
// speedup vs baseline: 1.5852x; 1.5852x over previous
#include <cuda_runtime.h>
#include <math.h>

#define TT 4096
#define EE 768
#define HH 12
#define DD 64
#define WIN 512
#define OUT_ELEMS (TT*EE)                 // 3145728
#define ATTN_ELEMS ((size_t)HH*TT*TT)     // 201326592

typedef unsigned long long ull;

// f32x2 packed-FMA helpers (sm_100+ PTX; ptxas never auto-fuses these)
#define PACK2(d, x)  asm("mov.b64 %0, {%1, %2};" : "=l"(d) : "f"(x), "f"(x))
#define FMA2(d, a, b) asm("fma.rn.f32x2 %0, %1, %2, %0;" : "+l"(d) : "l"(a), "l"(b))
#define UNPACK2(lo, hi, v) asm("mov.b64 {%0, %1}, %2;" : "=f"(lo), "=f"(hi) : "l"(v))

// ---------------- scratch (device globals: allocation-free) ----------------
__device__ __align__(16) float g_Q[TT*EE];
__device__ __align__(16) float g_K[TT*EE];
__device__ __align__(16) float g_V[TT*EE];
__device__ __align__(16) float g_ctx[TT*EE];
__device__ __align__(16) float g_d[HH*TT];

// ---------------- fp32 GEMM with f32x2: C[4096,768] = A[4096,768] @ W[768,768]
// BM=128, BN=64, BK=16, 256 threads, 8x4 micro-tile (4 cols = 2 f32x2 pairs).
__global__ __launch_bounds__(256) void sgemm_kernel(
    const float* __restrict__ A,
    const float* __restrict__ W0, const float* __restrict__ W1, const float* __restrict__ W2,
    float* __restrict__ Cout, int mode)
{
    const float* W;
    float* C;
    const float* Ain;
    if (mode == 0) {
        int z = blockIdx.z;
        W = (z == 0) ? W0 : (z == 1) ? W1 : W2;
        C = (z == 0) ? g_Q : (z == 1) ? g_K : g_V;
        Ain = A;
    } else {
        W = W0; C = Cout; Ain = g_ctx;
    }

    __shared__ float As[16][128];
    __shared__ float Ws[16][64];

    int tid = threadIdx.x;
    int tx = tid & 15, ty = tid >> 4;
    int n0 = blockIdx.x * 64;
    int m0 = blockIdx.y * 128;

    ull acc[8][2];
    #pragma unroll
    for (int r = 0; r < 8; r++) { acc[r][0] = 0ULL; acc[r][1] = 0ULL; }

    for (int k0 = 0; k0 < 768; k0 += 16) {
        #pragma unroll
        for (int it = 0; it < 2; it++) {
            int idx = tid + it * 256;
            int row = idx >> 2;
            int kq = (idx & 3) * 4;
            float4 v = *(const float4*)(Ain + (size_t)(m0 + row) * 768 + k0 + kq);
            As[kq + 0][row] = v.x;
            As[kq + 1][row] = v.y;
            As[kq + 2][row] = v.z;
            As[kq + 3][row] = v.w;
        }
        {
            int kk = tid >> 4;
            int nq = (tid & 15) * 4;
            *(float4*)&Ws[kk][nq] = *(const float4*)(W + (size_t)(k0 + kk) * 768 + n0 + nq);
        }
        __syncthreads();

        #pragma unroll
        for (int kk = 0; kk < 16; kk++) {
            float4 a0 = *(float4*)&As[kk][ty * 8];
            float4 a1 = *(float4*)&As[kk][ty * 8 + 4];
            ull Ap[8];
            PACK2(Ap[0], a0.x); PACK2(Ap[1], a0.y); PACK2(Ap[2], a0.z); PACK2(Ap[3], a0.w);
            PACK2(Ap[4], a1.x); PACK2(Ap[5], a1.y); PACK2(Ap[6], a1.z); PACK2(Ap[7], a1.w);
            ull b0 = *(const ull*)&Ws[kk][tx * 4];      // 16B-aligned
            ull b1 = *(const ull*)&Ws[kk][tx * 4 + 2];
            #pragma unroll
            for (int r = 0; r < 8; r++) {
                FMA2(acc[r][0], Ap[r], b0);
                FMA2(acc[r][1], Ap[r], b1);
            }
        }
        __syncthreads();
    }

    #pragma unroll
    for (int r = 0; r < 8; r++) {
        float4 v;
        UNPACK2(v.x, v.y, acc[r][0]);
        UNPACK2(v.z, v.w, acc[r][1]);
        *(float4*)(C + (size_t)(m0 + ty * 8 + r) * 768 + n0 + tx * 4) = v;
    }
}

// ---------------- d bias: d[h,t] = K[t]·u[h] - mean_t(K[t]·u[h]) ------------
__global__ __launch_bounds__(1024) void dbias_kernel(const float* __restrict__ u)
{
    int h = blockIdx.x, tid = threadIdx.x;
    __shared__ float su[64];
    __shared__ float red[32];
    if (tid < 64) su[tid] = u[h * 64 + tid];
    __syncthreads();

    float vals[4];
    float lsum = 0.f;
    #pragma unroll
    for (int j = 0; j < 4; j++) {
        int t = j * 1024 + tid;
        const float4* kp = (const float4*)(g_K + (size_t)t * 768 + h * 64);
        float dot = 0.f;
        #pragma unroll
        for (int q = 0; q < 16; q++) {
            float4 kv = kp[q];
            dot += kv.x * su[q * 4] + kv.y * su[q * 4 + 1] + kv.z * su[q * 4 + 2] + kv.w * su[q * 4 + 3];
        }
        vals[j] = dot;
        lsum += dot;
    }
    #pragma unroll
    for (int o = 16; o > 0; o >>= 1) lsum += __shfl_xor_sync(0xffffffffu, lsum, o);
    if ((tid & 31) == 0) red[tid >> 5] = lsum;
    __syncthreads();
    if (tid < 32) {
        float v = red[tid];
        #pragma unroll
        for (int o = 16; o > 0; o >>= 1) v += __shfl_xor_sync(0xffffffffu, v, o);
        if (tid == 0) red[0] = v * (1.0f / 4096.0f);
    }
    __syncthreads();
    float mean = red[0];
    #pragma unroll
    for (int j = 0; j < 4; j++)
        g_d[h * 4096 + j * 1024 + tid] = vals[j] - mean;
}

// ---------------- attention: 64 query rows per block -----------------------
// smem: sQq/sKq [64][65] row-major; sQkT/sKkT [64][66] d-major (transposed,
// even stride for LDS.64); sKkT reused row-major [64][66] as V tile in phase 3.
// sL 64x577, sd 576, rowS 64.
#define LW 577
#define SMEM_FLOATS (2*64*65 + 2*64*66 + 64*LW + 576 + 64)
#define SMEM_BYTES (SMEM_FLOATS * 4)

__global__ __launch_bounds__(256) void attn_kernel(
    const float* __restrict__ gates, float* __restrict__ attn_out)
{
    extern __shared__ float sm[];
    float (*sQq)[65] = (float(*)[65])sm;
    float (*sKq)[65] = sQq + 64;
    float (*sQkT)[66] = (float(*)[66])(sKq + 64);   // [d][col]
    float (*sKkT)[66] = sQkT + 64;                  // [d][col]; also V [row][col]
    float* sL = (float*)(sKkT + 64);      // 64 * 577
    float* sd = sL + 64 * LW;             // 576
    float* rowS = sd + 576;               // 64 (1/rowsum)

    int h = blockIdx.y;
    int t0 = blockIdx.x * 64;
    int tid = threadIdx.x;
    int sb = t0 - 512; if (sb < 0) sb = 0;
    int L = t0 + 64 - sb;                 // multiple of 64, <= 576

    // ---- fused zero-fill of this block's out-of-band attn region ----
    // rows [t0,t0+64) of head h: cols [0,sb) and [t0+64,TT). Fire-and-forget
    // stores; they drain on the idle DRAM path while we do FFMA below.
    {
        const float4 z4 = make_float4(0.f, 0.f, 0.f, 0.f);
        size_t rowbase = (size_t)h * TT * TT + (size_t)t0 * TT;
        int leftq = sb >> 2;                   // sb multiple of 64
        int right0 = t0 + 64;
        int rightq = (TT - right0) >> 2;
        for (int r = 0; r < 64; r++) {
            float4* bp = (float4*)(attn_out + rowbase + (size_t)r * TT);
            for (int c = tid; c < leftq; c += 256) bp[c] = z4;
            float4* rp4 = (float4*)(attn_out + rowbase + (size_t)r * TT + right0);
            for (int c = tid; c < rightq; c += 256) rp4[c] = z4;
        }
    }

    // gate softmax (every thread, cheap + uniform)
    float g0 = gates[h * 3 + 0], g1 = gates[h * 3 + 1], g2 = gates[h * 3 + 2];
    float gm = fmaxf(g0, fmaxf(g1, g2));
    float e0 = __expf(g0 - gm), e1 = __expf(g1 - gm), e2 = __expf(g2 - gm);
    float gi = 1.0f / (e0 + e1 + e2);
    float wstd = e0 * gi, wrec = e1 * gi, wdisc = e2 * gi;

    // load Q, K for query rows (row-major, scalar smem stores) + d band
    for (int i = tid; i < 64 * 16; i += 256) {
        int row = i >> 4;
        int c4 = (i & 15) * 4;
        float4 q = *(const float4*)(g_Q + (size_t)(t0 + row) * 768 + h * 64 + c4);
        float4 k = *(const float4*)(g_K + (size_t)(t0 + row) * 768 + h * 64 + c4);
        sQq[row][c4 + 0] = q.x; sQq[row][c4 + 1] = q.y; sQq[row][c4 + 2] = q.z; sQq[row][c4 + 3] = q.w;
        sKq[row][c4 + 0] = k.x; sKq[row][c4 + 1] = k.y; sKq[row][c4 + 2] = k.z; sKq[row][c4 + 3] = k.w;
    }
    for (int i = tid; i < L; i += 256) sd[i] = g_d[h * 4096 + sb + i];

    int tx = tid & 15, ty = tid >> 4;
    int i0 = ty * 4, j0 = tx * 4;
    int kt_lo = sb >> 6, kt_hi = t0 >> 6;

    // ---- phase 1: banded logits into sL ----
    for (int kt = kt_lo; kt <= kt_hi; kt++) {
        int s0 = kt * 64;
        __syncthreads();
        // load key-block Q,K transposed: sXkT[d][col] = X[s0+col][d]
        for (int i = tid; i < 64 * 16; i += 256) {
            int row = i >> 4;
            int c4 = (i & 15) * 4;
            float4 q = *(const float4*)(g_Q + (size_t)(s0 + row) * 768 + h * 64 + c4);
            float4 k = *(const float4*)(g_K + (size_t)(s0 + row) * 768 + h * 64 + c4);
            sQkT[c4 + 0][row] = q.x; sQkT[c4 + 1][row] = q.y; sQkT[c4 + 2][row] = q.z; sQkT[c4 + 3][row] = q.w;
            sKkT[c4 + 0][row] = k.x; sKkT[c4 + 1][row] = k.y; sKkT[c4 + 2][row] = k.z; sKkT[c4 + 3][row] = k.w;
        }
        __syncthreads();

        ull acc1[4][2], acc2[4][2];
        #pragma unroll
        for (int r = 0; r < 4; r++) {
            acc1[r][0] = 0ULL; acc1[r][1] = 0ULL;
            acc2[r][0] = 0ULL; acc2[r][1] = 0ULL;
        }

        #pragma unroll 8
        for (int d = 0; d < 64; d++) {
            ull Ap[4], KEp[4];
            #pragma unroll
            for (int r = 0; r < 4; r++) {
                PACK2(Ap[r],  sQq[i0 + r][d]);
                PACK2(KEp[r], sKq[i0 + r][d]);
            }
            ull B0  = *(const ull*)&sKkT[d][j0];      // (66*d + j0) even -> 8B aligned
            ull B1  = *(const ull*)&sKkT[d][j0 + 2];
            ull QK0 = *(const ull*)&sQkT[d][j0];
            ull QK1 = *(const ull*)&sQkT[d][j0 + 2];
            #pragma unroll
            for (int r = 0; r < 4; r++) {
                FMA2(acc1[r][0], Ap[r],  B0);
                FMA2(acc1[r][1], Ap[r],  B1);
                FMA2(acc2[r][0], KEp[r], QK0);
                FMA2(acc2[r][1], KEp[r], QK1);
            }
        }

        int soff = s0 - sb;
        #pragma unroll
        for (int r = 0; r < 4; r++) {
            int t = t0 + i0 + r;
            float a1v[4], a2v[4];
            UNPACK2(a1v[0], a1v[1], acc1[r][0]);
            UNPACK2(a1v[2], a1v[3], acc1[r][1]);
            UNPACK2(a2v[0], a2v[1], acc2[r][0]);
            UNPACK2(a2v[2], a2v[3], acc2[r][1]);
            #pragma unroll
            for (int c = 0; c < 4; c++) {
                int s = s0 + j0 + c;
                float v;
                if (s <= t && (t - s) <= 512)
                    v = (wstd * a1v[c] + wrec * a2v[c]) * 0.125f + wdisc * sd[soff + j0 + c];
                else
                    v = -1e30f;
                sL[(i0 + r) * LW + soff + j0 + c] = v;
            }
        }
    }
    __syncthreads();

    // ---- phase 2a: per-row max + exp (in place) + sum; 4 threads per row ----
    {
        int row = tid >> 2, l4 = tid & 3;
        float* rp = sL + row * LW;
        float m = -1e30f;
        for (int c = l4; c < L; c += 4) m = fmaxf(m, rp[c]);
        m = fmaxf(m, __shfl_xor_sync(0xffffffffu, m, 1));
        m = fmaxf(m, __shfl_xor_sync(0xffffffffu, m, 2));
        float s = 0.f;
        for (int c = l4; c < L; c += 4) {
            float ev = __expf(rp[c] - m);
            rp[c] = ev;
            s += ev;
        }
        s += __shfl_xor_sync(0xffffffffu, s, 1);
        s += __shfl_xor_sync(0xffffffffu, s, 2);
        if (l4 == 0) rowS[row] = 1.0f / s;
    }
    __syncthreads();

    // ---- phase 2b: write normalized attn band to gmem ----
    {
        size_t base = (size_t)h * TT * TT + (size_t)t0 * TT + sb;
        for (int i = 0; i < 64; i++) {
            float invs = rowS[i];
            const float* rp = sL + i * LW;
            float* op = attn_out + base + (size_t)i * TT;
            for (int c = tid; c < L; c += 256)
                op[c] = rp[c] * invs;
        }
    }

    // ---- phase 3: ctx = (exp) @ V, scaled by 1/rowsum at the end ----
    ull acc[4][2];
    #pragma unroll
    for (int r = 0; r < 4; r++) { acc[r][0] = 0ULL; acc[r][1] = 0ULL; }

    float (*sV)[66] = sKkT;   // reuse, now row-major [row][col]

    for (int kt = kt_lo; kt <= kt_hi; kt++) {
        int s0 = kt * 64;
        __syncthreads();
        for (int i = tid; i < 64 * 16; i += 256) {
            int row = i >> 4;
            int c4 = (i & 15) * 4;
            float4 v = *(const float4*)(g_V + (size_t)(s0 + row) * 768 + h * 64 + c4);
            sV[row][c4 + 0] = v.x; sV[row][c4 + 1] = v.y; sV[row][c4 + 2] = v.z; sV[row][c4 + 3] = v.w;
        }
        __syncthreads();
        int soff = s0 - sb;
        #pragma unroll 8
        for (int s = 0; s < 64; s++) {
            ull Pp[4];
            #pragma unroll
            for (int r = 0; r < 4; r++) PACK2(Pp[r], sL[(i0 + r) * LW + soff + s]);
            ull V0 = *(const ull*)&sV[s][j0];       // (66*s + j0) even -> aligned
            ull V1 = *(const ull*)&sV[s][j0 + 2];
            #pragma unroll
            for (int r = 0; r < 4; r++) {
                FMA2(acc[r][0], Pp[r], V0);
                FMA2(acc[r][1], Pp[r], V1);
            }
        }
    }

    #pragma unroll
    for (int r = 0; r < 4; r++) {
        float invs = rowS[i0 + r];
        float v0, v1, v2, v3;
        UNPACK2(v0, v1, acc[r][0]);
        UNPACK2(v2, v3, acc[r][1]);
        float* cp = g_ctx + (size_t)(t0 + i0 + r) * 768 + h * 64 + j0;
        cp[0] = v0 * invs; cp[1] = v1 * invs; cp[2] = v2 * invs; cp[3] = v3 * invs;
    }
}

// ---------------- launch ----------------------------------------------------
extern "C" void kernel_launch(void* const* d_in, const int* in_sizes, int n_in,
                              void* d_out, int out_size)
{
    const float* x     = (const float*)d_in[0];
    const float* Wq    = (const float*)d_in[1];
    const float* Wk    = (const float*)d_in[2];
    const float* Wv    = (const float*)d_in[3];
    const float* Wo    = (const float*)d_in[4];
    const float* gates = (const float*)d_in[5];
    const float* u     = (const float*)d_in[6];
    float* out  = (float*)d_out;
    float* attn = out + OUT_ELEMS;

    cudaFuncSetAttribute(attn_kernel, cudaFuncAttributeMaxDynamicSharedMemorySize, SMEM_BYTES);

    // QKV projections
    dim3 gq(12, 32, 3);
    sgemm_kernel<<<gq, 256>>>(x, Wq, Wk, Wv, nullptr, 0);

    // d bias from K
    dbias_kernel<<<12, 1024>>>(u);

    // banded gated attention (writes zeros + attn band + g_ctx; no memset needed)
    dim3 ga(64, 12, 1);
    attn_kernel<<<ga, 256, SMEM_BYTES>>>(gates, attn);

    // output projection
    dim3 go(12, 32, 1);
    sgemm_kernel<<<go, 256>>>(nullptr, Wo, nullptr, nullptr, out, 1);
}